// round 6
// baseline (speedup 1.0000x reference)
#include <cuda_runtime.h>

// DynamicRouting: votes [B=32, NIN=2048, NOUT=64, ATOMS=16] fp32, 3 iterations.
// logits are linear in accumulated pose P:  l = votes . (sum of prior poses)
//
// R6: votes are read from DRAM EXACTLY ONCE. 147 persistent blocks in 3
// independent groups of 49; each group holds one full batch b (2048 slices,
// 8MB) in SMEM across its 49 blocks (42 slices x 4KB = 168KB + 32KB reduce).
// All 3 routing iterations for that b run out of SMEM. Sync = per-b counters
// among the 49 blocks of one group only (no grid barriers -> no global
// convoy). A load-order ticket (g_turn) serializes the DRAM phases of the 3
// groups so one group streams at full bandwidth while the other two compute.

#define NB    32
#define NIN   2048
#define NOUT  64
#define ATOMS 16
#define SLICE (NOUT * ATOMS)      // 1024 floats = 4KB per (b,in)
#define NITER 3

#define NGROUP  3
#define BPG     49                // blocks per group (= per b)
#define GRID    (NGROUP * BPG)    // 147 blocks, 1 per SM -> all co-resident
#define THREADS 256
#define NWARP   8
#define VB_MAX  42                // max slices per block: ceil(2048/49)

// dynamic smem: VB[VB_MAX][SLICE] + RB[NWARP][SLICE]
#define SMEM_BYTES ((VB_MAX + NWARP) * SLICE * 4)   // 204800

__device__ __align__(256) float g_preact[NITER][NB * SLICE];
__device__ int g_done[2][NB];       // arrivals after iter0 / iter1 per b
__device__ int g_loaddone[NB];      // blocks that finished loading b
__device__ volatile int g_turn;     // next b allowed to load (b-order ticket)

__global__ void init_kernel() {
    int idx = blockIdx.x * blockDim.x + threadIdx.x;
    if (idx < NITER * NB * SLICE)
        (&g_preact[0][0])[idx] = 0.0f;
    if (idx < 2 * NB) (&g_done[0][0])[idx] = 0;
    if (idx < NB)     g_loaddone[idx] = 0;
    if (idx == 0)     g_turn = 0;
}

__device__ __forceinline__ unsigned smem_u32(const void* p) {
    return (unsigned)__cvta_generic_to_shared(p);
}

// One 4KB slice gmem->smem: 8 x 16B per lane, coalesced, L2-only path.
__device__ __forceinline__ void cp_async_slice(unsigned dst, const float4* __restrict__ src,
                                               int lane) {
#pragma unroll
    for (int j = 0; j < 8; j++) {
        asm volatile("cp.async.cg.shared.global [%0], [%1], 16;\n" ::
                     "r"(dst + (unsigned)(lane + 32 * j) * 16u),
                     "l"(src + lane + 32 * j) : "memory");
    }
}

// Block reduce of per-warp acc via RB, then red.global into g_preact[it][b].
__device__ __forceinline__ void reduce_and_emit(const float4 acc[8], float* RB,
                                                int b, int it, int lane, int warp) {
    __syncthreads();   // RB free, all warps done reading smem votes this phase
    float4* rw = reinterpret_cast<float4*>(RB + warp * SLICE);
#pragma unroll
    for (int j = 0; j < 8; j++) rw[lane + 32 * j] = acc[j];
    __syncthreads();
#pragma unroll 1
    for (int t = threadIdx.x; t < SLICE / 4; t += THREADS) {
        float4 s = make_float4(0.f, 0.f, 0.f, 0.f);
#pragma unroll
        for (int w = 0; w < NWARP; w++) {
            float4 a = reinterpret_cast<const float4*>(RB + w * SLICE)[t];
            s.x += a.x; s.y += a.y; s.z += a.z; s.w += a.w;
        }
        float* out = &g_preact[it][b * SLICE + 4 * t];
        asm volatile("red.global.add.v4.f32 [%0], {%1, %2, %3, %4};\n"
                     :: "l"(out), "f"(s.x), "f"(s.y), "f"(s.z), "f"(s.w)
                     : "memory");
    }
}

// Arrive + wait among the 49 blocks of this b (release/acquire via fences).
__device__ __forceinline__ void arrive_and_wait(int* ctr) {
    __threadfence();          // each thread's red.global visible before arrival
    __syncthreads();          // all threads fenced before tid0 arrives
    if (threadIdx.x == 0) {
        atomicAdd(ctr, 1);
        while (*((volatile int*)ctr) < BPG) __nanosleep(32);
        __threadfence();      // acquire: others' preact writes now visible
    }
    __syncthreads();
}

// P += squash(pre[b-slice]) in the lane layout (out = lane/4 + 8j).
__device__ __forceinline__ void add_pose(float4 P[8], const float* __restrict__ pre,
                                         int lane) {
    const float4* p4 = reinterpret_cast<const float4*>(pre);
#pragma unroll
    for (int j = 0; j < 8; j++) {
        float4 pr = p4[lane + 32 * j];
        float sq = pr.x * pr.x + pr.y * pr.y + pr.z * pr.z + pr.w * pr.w;
        sq += __shfl_xor_sync(0xffffffffu, sq, 1);
        sq += __shfl_xor_sync(0xffffffffu, sq, 2);
        float scale = (sq / (1.0f + sq)) * rsqrtf(sq + 1e-9f);
        P[j].x = fmaf(scale, pr.x, P[j].x);
        P[j].y = fmaf(scale, pr.y, P[j].y);
        P[j].z = fmaf(scale, pr.z, P[j].z);
        P[j].w = fmaf(scale, pr.w, P[j].w);
    }
}

// Lane layout per slice: lane holds float4 at slice pos 4*lane + 128*j (j=0..7)
// -> out = lane/4 + 8j, atoms 4*(lane&3)..+3.
__global__ __launch_bounds__(THREADS, 1) void route_persistent(const float* __restrict__ votes) {
    extern __shared__ float sm[];
    float* VB = sm;                      // [VB_MAX][SLICE] resident votes
    float* RB = sm + VB_MAX * SLICE;     // [NWARP][SLICE] reduce buffer

    const int lane = threadIdx.x & 31;
    const int warp = threadIdx.x >> 5;
    const int grp  = blockIdx.x / BPG;   // 0..2 -> b = grp, grp+3, ...
    const int blk  = blockIdx.x % BPG;

    const int lo = (blk * NIN) / BPG;
    const int hi = ((blk + 1) * NIN) / BPG;
    const int n  = hi - lo;              // 41 or 42 slices

    for (int b = grp; b < NB; b += NGROUP) {
        const float4* V = reinterpret_cast<const float4*>(votes)
                          + (size_t)(b * NIN + lo) * (SLICE / 4);

        // ---- load turn: keep one group on DRAM at a time (b-order ticket) ----
        if (threadIdx.x == 0)
            while (g_turn < b) __nanosleep(64);
        __syncthreads();

        // ---- load all my slices into resident smem ----
        for (int s = warp; s < n; s += NWARP)
            cp_async_slice(smem_u32(VB + s * SLICE), V + (size_t)s * (SLICE / 4), lane);
        asm volatile("cp.async.commit_group;\ncp.async.wait_group 0;\n" ::: "memory");
        __syncthreads();

        // release the DRAM ticket as soon as this b's data is fully in smem
        if (threadIdx.x == 0) {
            if (atomicAdd(&g_loaddone[b], 1) + 1 == BPG) {
                __threadfence();
                g_turn = b + 1;
            }
        }

        // ---- iter0: c uniform = 1/NOUT -> plain sum over slices ----
        float4 acc[8];
#pragma unroll
        for (int j = 0; j < 8; j++) acc[j] = make_float4(0.f, 0.f, 0.f, 0.f);
        for (int s = warp; s < n; s += NWARP) {
            const float4* sv = reinterpret_cast<const float4*>(VB + s * SLICE);
#pragma unroll
            for (int j = 0; j < 8; j++) {
                float4 v = sv[lane + 32 * j];
                acc[j].x += v.x; acc[j].y += v.y; acc[j].z += v.z; acc[j].w += v.w;
            }
        }
        {
            const float u = 1.0f / NOUT;
#pragma unroll
            for (int j = 0; j < 8; j++) {
                acc[j].x *= u; acc[j].y *= u; acc[j].z *= u; acc[j].w *= u;
            }
        }
        reduce_and_emit(acc, RB, b, 0, lane, warp);
        arrive_and_wait(&g_done[0][b]);

        // ---- P = pose0 ----
        float4 P[8];
#pragma unroll
        for (int j = 0; j < 8; j++) P[j] = make_float4(0.f, 0.f, 0.f, 0.f);
        add_pose(P, &g_preact[0][b * SLICE], lane);

        // ---- iters 1 and 2: softmax-weighted sums, votes from smem ----
#pragma unroll 1
        for (int it = 1; it < NITER; it++) {
#pragma unroll
            for (int j = 0; j < 8; j++) acc[j] = make_float4(0.f, 0.f, 0.f, 0.f);

            for (int s = warp; s < n; s += NWARP) {
                const float4* sv = reinterpret_cast<const float4*>(VB + s * SLICE);
                float4 v[8];
#pragma unroll
                for (int j = 0; j < 8; j++) v[j] = sv[lane + 32 * j];

                float l[8];
#pragma unroll
                for (int j = 0; j < 8; j++) {
                    float d = v[j].x * P[j].x + v[j].y * P[j].y
                            + v[j].z * P[j].z + v[j].w * P[j].w;
                    d += __shfl_xor_sync(0xffffffffu, d, 1);
                    d += __shfl_xor_sync(0xffffffffu, d, 2);
                    l[j] = d;
                }
                // softmax over 64 outs, no max shift (|l| <= ~16, fp32-safe)
                float ssum = 0.f;
#pragma unroll
                for (int j = 0; j < 8; j++) { l[j] = __expf(l[j]); ssum += l[j]; }
                ssum += __shfl_xor_sync(0xffffffffu, ssum, 4);
                ssum += __shfl_xor_sync(0xffffffffu, ssum, 8);
                ssum += __shfl_xor_sync(0xffffffffu, ssum, 16);
                float inv = 1.0f / ssum;
#pragma unroll
                for (int j = 0; j < 8; j++) {
                    float c = l[j] * inv;
                    acc[j].x = fmaf(c, v[j].x, acc[j].x);
                    acc[j].y = fmaf(c, v[j].y, acc[j].y);
                    acc[j].z = fmaf(c, v[j].z, acc[j].z);
                    acc[j].w = fmaf(c, v[j].w, acc[j].w);
                }
            }
            reduce_and_emit(acc, RB, b, it, lane, warp);
            if (it < NITER - 1) {
                arrive_and_wait(&g_done[it][b]);
                add_pose(P, &g_preact[it][b * SLICE], lane);
            }
            // after it==2: no wait; reduce_and_emit's syncthreads guarantees all
            // warps finished reading VB, so next b's load may overwrite it.
        }
    }
}

// Final: pose = squash(preact[2]); outputs pose [B,NOUT,ATOMS] + prob [B,NOUT].
__global__ void final_squash_kernel(float* __restrict__ d_out) {
    int idx = blockIdx.x * blockDim.x + threadIdx.x;  // (b*NOUT + out)
    if (idx >= NB * NOUT) return;

    const float* pre = &g_preact[NITER - 1][idx * ATOMS];
    float s[ATOMS];
    float sq = 0.f;
#pragma unroll
    for (int a = 0; a < ATOMS; a++) { s[a] = pre[a]; sq += s[a] * s[a]; }

    float scale = (sq / (1.0f + sq)) * rsqrtf(sq + 1e-9f);
#pragma unroll
    for (int a = 0; a < ATOMS; a++)
        d_out[idx * ATOMS + a] = s[a] * scale;
    float psq = scale * scale * sq;
    d_out[NB * NOUT * ATOMS + idx] = sqrtf(psq + 1e-9f);
}

extern "C" void kernel_launch(void* const* d_in, const int* in_sizes, int n_in,
                              void* d_out, int out_size) {
    const float* votes = (const float*)d_in[0];
    float* out = (float*)d_out;

    cudaFuncSetAttribute(route_persistent,
                         cudaFuncAttributeMaxDynamicSharedMemorySize, SMEM_BYTES);

    init_kernel<<<(NITER * NB * SLICE + 255) / 256, 256>>>();
    route_persistent<<<GRID, THREADS, SMEM_BYTES>>>(votes);
    final_squash_kernel<<<(NB * NOUT + 255) / 256, 256>>>(out);
}

// round 11
// speedup vs baseline: 1.5733x; 1.5733x over previous
#include <cuda_runtime.h>

// DynamicRouting: votes [B=32, NIN=2048, NOUT=64, ATOMS=16] fp32, 3 iterations.
// logits are linear in accumulated pose P:  l = votes . (sum of prior poses)
// Each iteration = one streaming pass over the 256MB votes tensor (proven
// fastest architecture; all sync-for-reuse schemes regressed: R4/R5/R6).
//
// R7: persistent flat-wave grid (592 = 148 SMs x 4 blocks, exactly one wave,
// <1% imbalance). Warps own contiguous global slice ranges across the flat
// [B*NIN] axis; cp.async DEPTH=3 pipeline streams across b boundaries.
// Per-warp red.v4 emission (no block reduce, zero __syncthreads in route).
// No init kernel: device globals load zeroed; squash re-zeros preact and
// overwrites g_P on pass 0 -> state self-restores across graph replays.

#define NB    32
#define NIN   2048
#define NOUT  64
#define ATOMS 16
#define SLICE (NOUT * ATOMS)      // 1024 floats = 4KB per (b,in)
#define GTOT  (NB * NIN)          // 65536 global slices

__device__ __align__(256) float g_preact[NB * SLICE];  // zero at load; squash re-zeros
__device__ __align__(256) float g_P[NB * SLICE];       // overwritten each launch

#define NBLK    592               // 148 SMs x 4 blocks -> exactly one wave
#define WARPS_PB 4
#define NWARPT  (NBLK * WARPS_PB)
#define DEPTH   3

__device__ __forceinline__ unsigned smem_u32(const void* p) {
    return (unsigned)__cvta_generic_to_shared(p);
}

// One 4KB slice gmem->smem: 8 x 16B per lane, fully coalesced; own commit group.
__device__ __forceinline__ void cp_async_slice(unsigned dst, const float4* __restrict__ src,
                                               int lane) {
#pragma unroll
    for (int j = 0; j < 8; j++) {
        asm volatile("cp.async.cg.shared.global [%0], [%1], 16;\n" ::
                     "r"(dst + (unsigned)(lane + 32 * j) * 16u),
                     "l"(src + lane + 32 * j) : "memory");
    }
    asm volatile("cp.async.commit_group;\n" ::: "memory");
}

__device__ __forceinline__ void cp_async_wait(int n) {
    if (n <= 0)      asm volatile("cp.async.wait_group 0;\n" ::: "memory");
    else if (n == 1) asm volatile("cp.async.wait_group 1;\n" ::: "memory");
    else             asm volatile("cp.async.wait_group 2;\n" ::: "memory");
}

// Emit this warp's accumulator for batch b via vectorized global reduction.
__device__ __forceinline__ void emit_acc(const float4 acc[8], int b, int lane, float mul) {
    float* out = g_preact + b * SLICE + 4 * lane;
#pragma unroll
    for (int j = 0; j < 8; j++) {
        asm volatile("red.global.add.v4.f32 [%0], {%1, %2, %3, %4};\n"
                     :: "l"(out + 128 * j),
                        "f"(acc[j].x * mul), "f"(acc[j].y * mul),
                        "f"(acc[j].z * mul), "f"(acc[j].w * mul)
                     : "memory");
    }
}

__device__ __forceinline__ void load_P(float4 P[8], int b, int lane) {
    const float4* P4 = reinterpret_cast<const float4*>(g_P + b * SLICE);
#pragma unroll
    for (int j = 0; j < 8; j++) P[j] = P4[lane + 32 * j];
}

// Lane layout per slice: lane holds float4 at slice pos 4*lane + 128*j (j=0..7)
// -> out = lane/4 + 8j, atoms 4*(lane&3)..+3.
template <bool UNIFORM>
__global__ __launch_bounds__(128, 4) void route_kernel(const float* __restrict__ votes) {
    __shared__ float stage[WARPS_PB][DEPTH][SLICE];   // 48KB

    const int lane = threadIdx.x & 31;
    const int warp = threadIdx.x >> 5;
    const int wid  = blockIdx.x * WARPS_PB + warp;    // 0..2367

    // contiguous global slice range for this warp (~27-28 slices)
    const int wlo = (int)(((long long)wid * GTOT) / NWARPT);
    const int whi = (int)(((long long)(wid + 1) * GTOT) / NWARPT);
    const int n   = whi - wlo;

    const float4* V = reinterpret_cast<const float4*>(votes);

    unsigned sbase[DEPTH];
#pragma unroll
    for (int d = 0; d < DEPTH; d++) sbase[d] = smem_u32(&stage[warp][d][0]);

    // prologue: fill pipeline
    int committed = 0;
#pragma unroll
    for (int k = 0; k < DEPTH; k++)
        if (k < n) { cp_async_slice(sbase[k], V + (size_t)(wlo + k) * (SLICE / 4), lane); committed++; }

    int cur_b = wlo >> 11;           // NIN = 2048
    float4 P[8];
    if (!UNIFORM) load_P(P, cur_b, lane);

    float4 acc[8];
#pragma unroll
    for (int j = 0; j < 8; j++) acc[j] = make_float4(0.f, 0.f, 0.f, 0.f);

    const float umul = UNIFORM ? (1.0f / NOUT) : 1.0f;

    for (int i = 0; i < n; i++) {
        const int gs = wlo + i;
        const int b  = gs >> 11;
        if (b != cur_b) {            // at most once per warp
            emit_acc(acc, cur_b, lane, umul);
#pragma unroll
            for (int j = 0; j < 8; j++) acc[j] = make_float4(0.f, 0.f, 0.f, 0.f);
            cur_b = b;
            if (!UNIFORM) load_P(P, cur_b, lane);
        }

        cp_async_wait(committed - i - 1);

        const float4* sv = reinterpret_cast<const float4*>(&stage[warp][i % DEPTH][0]);
        float4 v[8];
#pragma unroll
        for (int j = 0; j < 8; j++) v[j] = sv[lane + 32 * j];

        if (i + DEPTH < n) {
            cp_async_slice(sbase[i % DEPTH], V + (size_t)(gs + DEPTH) * (SLICE / 4), lane);
            committed++;
        }

        if (UNIFORM) {
            // softmax(0) = uniform 1/NOUT: plain sum, scaled at emit
#pragma unroll
            for (int j = 0; j < 8; j++) {
                acc[j].x += v[j].x; acc[j].y += v[j].y;
                acc[j].z += v[j].z; acc[j].w += v[j].w;
            }
        } else {
            // logits: 16-atom dot via 4-lane xor reduce (4 lanes share one out)
            float l[8];
#pragma unroll
            for (int j = 0; j < 8; j++) {
                float d = v[j].x * P[j].x + v[j].y * P[j].y
                        + v[j].z * P[j].z + v[j].w * P[j].w;
                d += __shfl_xor_sync(0xffffffffu, d, 1);
                d += __shfl_xor_sync(0xffffffffu, d, 2);
                l[j] = d;
            }
            // softmax over 64 outs, no max shift (|l| small, fp32-safe)
            float s = 0.f;
#pragma unroll
            for (int j = 0; j < 8; j++) { l[j] = __expf(l[j]); s += l[j]; }
            s += __shfl_xor_sync(0xffffffffu, s, 4);
            s += __shfl_xor_sync(0xffffffffu, s, 8);
            s += __shfl_xor_sync(0xffffffffu, s, 16);
            float inv = 1.0f / s;
#pragma unroll
            for (int j = 0; j < 8; j++) {
                float c = l[j] * inv;
                acc[j].x = fmaf(c, v[j].x, acc[j].x);
                acc[j].y = fmaf(c, v[j].y, acc[j].y);
                acc[j].z = fmaf(c, v[j].z, acc[j].z);
                acc[j].w = fmaf(c, v[j].w, acc[j].w);
            }
        }
    }
    emit_acc(acc, cur_b, lane, umul);
}

// squash(preact) -> pose; g_P = (first ? pose : g_P + pose); preact -> 0
// (self-restoring state for graph replay). On last pass, write outputs.
__global__ void squash_kernel(float* __restrict__ d_out, int first, int last) {
    int idx = blockIdx.x * blockDim.x + threadIdx.x;  // (b*NOUT + out)
    if (idx >= NB * NOUT) return;

    float* pre = g_preact + idx * ATOMS;
    float s[ATOMS];
    float sq = 0.f;
#pragma unroll
    for (int a = 0; a < ATOMS; a++) { s[a] = pre[a]; sq += s[a] * s[a]; }

    float scale = (sq / (1.0f + sq)) * rsqrtf(sq + 1e-9f);

    float* Pp = g_P + idx * ATOMS;
#pragma unroll
    for (int a = 0; a < ATOMS; a++) {
        float p = s[a] * scale;
        pre[a] = 0.0f;                              // restore zeros for next pass/replay
        if (last) d_out[idx * ATOMS + a] = p;       // pose_out [B, NOUT, ATOMS]
        else      Pp[a] = first ? p : (Pp[a] + p);  // accumulated pose
    }
    if (last) {
        float psq = scale * scale * sq;             // sum(pose^2)
        d_out[NB * NOUT * ATOMS + idx] = sqrtf(psq + 1e-9f);  // prob_out [B, NOUT]
    }
}

extern "C" void kernel_launch(void* const* d_in, const int* in_sizes, int n_in,
                              void* d_out, int out_size) {
    const float* votes = (const float*)d_in[0];
    float* out = (float*)d_out;

    route_kernel<true><<<NBLK, 128>>>(votes);
    squash_kernel<<<(NB * NOUT + 255) / 256, 256>>>(out, 1, 0);
    route_kernel<false><<<NBLK, 128>>>(votes);
    squash_kernel<<<(NB * NOUT + 255) / 256, 256>>>(out, 0, 0);
    route_kernel<false><<<NBLK, 128>>>(votes);
    squash_kernel<<<(NB * NOUT + 255) / 256, 256>>>(out, 0, 1);
}

// round 12
// speedup vs baseline: 1.6015x; 1.0179x over previous
#include <cuda_runtime.h>

// DynamicRouting: votes [B=32, NIN=2048, NOUT=64, ATOMS=16] fp32, 3 iterations.
// logits are linear in accumulated pose P:  l = votes . (sum of prior poses)
// Each iteration = one streaming pass over the 256MB votes tensor (proven
// fastest architecture; sync-for-reuse schemes regressed: R4/R5/R6).
//
// R12: no inter-iteration squash kernels. Per-iteration preact buffers;
// route pass `it` derives P per-warp by redundantly squashing preact[0..it-1]
// (L2-hot, ~100 cycles, overlapped with cp.async prologue). Kernel boundaries
// are the only sync. Final squash uses 4 threads/capsule (coalesced float4)
// and re-zeros all preact buffers for graph-replay self-restoration.
// Launch chain: route<0>, route<1>, route<2>, final_squash  (6 -> 4 kernels).

#define NB    32
#define NIN   2048
#define NOUT  64
#define ATOMS 16
#define SLICE (NOUT * ATOMS)      // 1024 floats = 4KB per (b,in)
#define GTOT  (NB * NIN)          // 65536 global slices
#define NITER 3

__device__ __align__(256) float g_preact[NITER][NB * SLICE];  // zero at load; squash re-zeros

#define NBLK    592               // 148 SMs x 4 blocks -> exactly one wave
#define WARPS_PB 4
#define NWARPT  (NBLK * WARPS_PB)
#define DEPTH   3

__device__ __forceinline__ unsigned smem_u32(const void* p) {
    return (unsigned)__cvta_generic_to_shared(p);
}

// One 4KB slice gmem->smem: 8 x 16B per lane, fully coalesced; own commit group.
__device__ __forceinline__ void cp_async_slice(unsigned dst, const float4* __restrict__ src,
                                               int lane) {
#pragma unroll
    for (int j = 0; j < 8; j++) {
        asm volatile("cp.async.cg.shared.global [%0], [%1], 16;\n" ::
                     "r"(dst + (unsigned)(lane + 32 * j) * 16u),
                     "l"(src + lane + 32 * j) : "memory");
    }
    asm volatile("cp.async.commit_group;\n" ::: "memory");
}

__device__ __forceinline__ void cp_async_wait(int n) {
    if (n <= 0)      asm volatile("cp.async.wait_group 0;\n" ::: "memory");
    else if (n == 1) asm volatile("cp.async.wait_group 1;\n" ::: "memory");
    else             asm volatile("cp.async.wait_group 2;\n" ::: "memory");
}

// Emit this warp's accumulator for batch b into g_preact[IT][b] (vector red).
template <int IT>
__device__ __forceinline__ void emit_acc(const float4 acc[8], int b, int lane, float mul) {
    float* out = &g_preact[IT][b * SLICE + 4 * lane];
#pragma unroll
    for (int j = 0; j < 8; j++) {
        asm volatile("red.global.add.v4.f32 [%0], {%1, %2, %3, %4};\n"
                     :: "l"(out + 128 * j),
                        "f"(acc[j].x * mul), "f"(acc[j].y * mul),
                        "f"(acc[j].z * mul), "f"(acc[j].w * mul)
                     : "memory");
    }
}

// P += squash(preact[k][b]) in the lane layout (out = lane/4 + 8j).
__device__ __forceinline__ void add_pose(float4 P[8], const float* __restrict__ pre,
                                         int lane) {
    const float4* p4 = reinterpret_cast<const float4*>(pre);
#pragma unroll
    for (int j = 0; j < 8; j++) {
        float4 pr = p4[lane + 32 * j];
        float sq = pr.x * pr.x + pr.y * pr.y + pr.z * pr.z + pr.w * pr.w;
        sq += __shfl_xor_sync(0xffffffffu, sq, 1);
        sq += __shfl_xor_sync(0xffffffffu, sq, 2);
        float scale = (sq / (1.0f + sq)) * rsqrtf(sq + 1e-9f);
        P[j].x = fmaf(scale, pr.x, P[j].x);
        P[j].y = fmaf(scale, pr.y, P[j].y);
        P[j].z = fmaf(scale, pr.z, P[j].z);
        P[j].w = fmaf(scale, pr.w, P[j].w);
    }
}

template <int ITER>
__device__ __forceinline__ void derive_P(float4 P[8], int b, int lane) {
#pragma unroll
    for (int j = 0; j < 8; j++) P[j] = make_float4(0.f, 0.f, 0.f, 0.f);
#pragma unroll
    for (int k = 0; k < ITER; k++)
        add_pose(P, &g_preact[k][b * SLICE], lane);
}

// Lane layout per slice: lane holds float4 at slice pos 4*lane + 128*j (j=0..7)
// -> out = lane/4 + 8j, atoms 4*(lane&3)..+3.
template <int ITER>
__global__ __launch_bounds__(128, 4) void route_kernel(const float* __restrict__ votes) {
    __shared__ float stage[WARPS_PB][DEPTH][SLICE];   // 48KB

    const int lane = threadIdx.x & 31;
    const int warp = threadIdx.x >> 5;
    const int wid  = blockIdx.x * WARPS_PB + warp;    // 0..2367

    // contiguous global slice range for this warp (~27-28 slices)
    const int wlo = (int)(((long long)wid * GTOT) / NWARPT);
    const int whi = (int)(((long long)(wid + 1) * GTOT) / NWARPT);
    const int n   = whi - wlo;

    const float4* V = reinterpret_cast<const float4*>(votes);

    unsigned sbase[DEPTH];
#pragma unroll
    for (int d = 0; d < DEPTH; d++) sbase[d] = smem_u32(&stage[warp][d][0]);

    // prologue: fill pipeline (overlaps with P derivation below)
    int committed = 0;
#pragma unroll
    for (int k = 0; k < DEPTH; k++)
        if (k < n) { cp_async_slice(sbase[k], V + (size_t)(wlo + k) * (SLICE / 4), lane); committed++; }

    int cur_b = wlo >> 11;           // NIN = 2048
    float4 P[8];
    derive_P<ITER>(P, cur_b, lane);  // no-op loads for ITER==0

    float4 acc[8];
#pragma unroll
    for (int j = 0; j < 8; j++) acc[j] = make_float4(0.f, 0.f, 0.f, 0.f);

    const float umul = (ITER == 0) ? (1.0f / NOUT) : 1.0f;

    for (int i = 0; i < n; i++) {
        const int gs = wlo + i;
        const int b  = gs >> 11;
        if (b != cur_b) {            // at most once per warp
            emit_acc<ITER>(acc, cur_b, lane, umul);
#pragma unroll
            for (int j = 0; j < 8; j++) acc[j] = make_float4(0.f, 0.f, 0.f, 0.f);
            cur_b = b;
            derive_P<ITER>(P, cur_b, lane);
        }

        cp_async_wait(committed - i - 1);

        const float4* sv = reinterpret_cast<const float4*>(&stage[warp][i % DEPTH][0]);
        float4 v[8];
#pragma unroll
        for (int j = 0; j < 8; j++) v[j] = sv[lane + 32 * j];

        if (i + DEPTH < n) {
            cp_async_slice(sbase[i % DEPTH], V + (size_t)(gs + DEPTH) * (SLICE / 4), lane);
            committed++;
        }

        if (ITER == 0) {
            // softmax(0) = uniform 1/NOUT: plain sum, scaled at emit
#pragma unroll
            for (int j = 0; j < 8; j++) {
                acc[j].x += v[j].x; acc[j].y += v[j].y;
                acc[j].z += v[j].z; acc[j].w += v[j].w;
            }
        } else {
            // logits: 16-atom dot via 4-lane xor reduce (4 lanes share one out)
            float l[8];
#pragma unroll
            for (int j = 0; j < 8; j++) {
                float d = v[j].x * P[j].x + v[j].y * P[j].y
                        + v[j].z * P[j].z + v[j].w * P[j].w;
                d += __shfl_xor_sync(0xffffffffu, d, 1);
                d += __shfl_xor_sync(0xffffffffu, d, 2);
                l[j] = d;
            }
            // softmax over 64 outs, no max shift (|l| small, fp32-safe)
            float s = 0.f;
#pragma unroll
            for (int j = 0; j < 8; j++) { l[j] = __expf(l[j]); s += l[j]; }
            s += __shfl_xor_sync(0xffffffffu, s, 4);
            s += __shfl_xor_sync(0xffffffffu, s, 8);
            s += __shfl_xor_sync(0xffffffffu, s, 16);
            float inv = 1.0f / s;
#pragma unroll
            for (int j = 0; j < 8; j++) {
                float c = l[j] * inv;
                acc[j].x = fmaf(c, v[j].x, acc[j].x);
                acc[j].y = fmaf(c, v[j].y, acc[j].y);
                acc[j].z = fmaf(c, v[j].z, acc[j].z);
                acc[j].w = fmaf(c, v[j].w, acc[j].w);
            }
        }
    }
    emit_acc<ITER>(acc, cur_b, lane, umul);
}

// Final: pose = squash(preact[2]) -> outputs; re-zero ALL preact buffers
// (graph-replay self-restore). 4 threads per capsule, coalesced float4.
#define SQ_THREADS 256
#define SQ_BLOCKS  32          // 32*256 = 8192 = 4 * 2048 capsules
__global__ void final_squash_kernel(float* __restrict__ d_out) {
    const int tid  = blockIdx.x * SQ_THREADS + threadIdx.x;   // 0..8191
    const int cap  = tid >> 2;           // capsule index (b*NOUT + out)
    const int part = tid & 3;            // which float4 of the 16 atoms

    const float4* pre4 = reinterpret_cast<const float4*>(&g_preact[NITER - 1][cap * ATOMS]);
    float4 pr = pre4[part];
    float sq = pr.x * pr.x + pr.y * pr.y + pr.z * pr.z + pr.w * pr.w;
    sq += __shfl_xor_sync(0xffffffffu, sq, 1);
    sq += __shfl_xor_sync(0xffffffffu, sq, 2);

    float scale = (sq / (1.0f + sq)) * rsqrtf(sq + 1e-9f);

    float4* out4 = reinterpret_cast<float4*>(d_out + cap * ATOMS);
    out4[part] = make_float4(pr.x * scale, pr.y * scale, pr.z * scale, pr.w * scale);
    if (part == 0) {
        float psq = scale * scale * sq;                       // sum(pose^2)
        d_out[NB * NOUT * ATOMS + cap] = sqrtf(psq + 1e-9f);  // prob_out [B, NOUT]
    }

    // re-zero all preact buffers: 3*32768 float4s over 8192 threads = 12 each
    float4* pz = reinterpret_cast<float4*>(&g_preact[0][0]);
#pragma unroll
    for (int k = 0; k < (NITER * NB * SLICE / 4) / (SQ_BLOCKS * SQ_THREADS); k++)
        pz[tid + k * SQ_BLOCKS * SQ_THREADS] = make_float4(0.f, 0.f, 0.f, 0.f);
}

extern "C" void kernel_launch(void* const* d_in, const int* in_sizes, int n_in,
                              void* d_out, int out_size) {
    const float* votes = (const float*)d_in[0];
    float* out = (float*)d_out;

    route_kernel<0><<<NBLK, 128>>>(votes);
    route_kernel<1><<<NBLK, 128>>>(votes);
    route_kernel<2><<<NBLK, 128>>>(votes);
    final_squash_kernel<<<SQ_BLOCKS, SQ_THREADS>>>(out);
}